// round 15
// baseline (speedup 1.0000x reference)
#include <cuda_runtime.h>
#include <cuda_fp16.h>
#include <cstdint>
#include <math.h>

// ---------------- problem constants ----------------
#define B_  32
#define T_  512
#define D_  768
#define H_  12
#define E_  6
#define HE_ 72
#define QKVN_ 216
#define DFF_ 3072
#define M_  (B_ * T_)        // 16384
#define EPS_ 1e-5f
#define KPAD_ 128            // proj K padded 72 -> 128 (divisible by BK=64)

// ---------------- scratch (device globals) ----------------
__device__ __half g_xn [M_ * D_];          // LN output (fp16)
__device__ __half g_qkv[M_ * QKVN_];       // q|k|v per row (fp16)
__device__ __half g_o  [M_ * KPAD_];       // attention out, padded to 128 cols (fp16)
__device__ float  g_x2 [M_ * D_];          // residual 1 (fp32)
__device__ __half g_h  [M_ * DFF_];        // FFN hidden (fp16)
__device__ __half g_bqkvt[256 * D_];       // QKV weights [256(n pad), 768] fp16 K-major
__device__ __half g_bot[D_ * KPAD_];       // Wo^T [768, 128] fp16 (K padded)
__device__ __half g_b1t[DFF_ * D_];        // W1^T [3072, 768] fp16
__device__ __half g_b2t[D_ * DFF_];        // W2^T [768, 3072] fp16
__device__ int    g_ctr1, g_ctr2;          // dynamic tile counters (reset each launch in prep)

// ---------------- helpers ----------------
__device__ __forceinline__ void cpasync16(void* dst, const void* src) {
    uint32_t d;
    asm("{ .reg .u64 t; cvta.to.shared.u64 t, %1; cvt.u32.u64 %0, t; }" : "=r"(d) : "l"(dst));
    asm volatile("cp.async.cg.shared.global [%0], [%1], 16;" :: "r"(d), "l"(src));
}
#define CP_COMMIT() asm volatile("cp.async.commit_group;")

__device__ __forceinline__ void mma_fp16(float* c, const uint32_t* a, const uint32_t* b) {
    asm volatile(
        "mma.sync.aligned.m16n8k16.row.col.f32.f16.f16.f32 "
        "{%0,%1,%2,%3}, {%4,%5,%6,%7}, {%8,%9}, {%0,%1,%2,%3};"
        : "+f"(c[0]), "+f"(c[1]), "+f"(c[2]), "+f"(c[3])
        : "r"(a[0]), "r"(a[1]), "r"(a[2]), "r"(a[3]), "r"(b[0]), "r"(b[1]));
}
__device__ __forceinline__ void ldsm4(uint32_t* r, const __half* p) {
    uint32_t a;
    asm("{ .reg .u64 t; cvta.to.shared.u64 t, %1; cvt.u32.u64 %0, t; }" : "=r"(a) : "l"(p));
    asm volatile("ldmatrix.sync.aligned.m8n8.x4.shared.b16 {%0,%1,%2,%3}, [%4];"
        : "=r"(r[0]), "=r"(r[1]), "=r"(r[2]), "=r"(r[3]) : "r"(a));
}
__device__ __forceinline__ float ex2f(float x) {
    float r;
    asm("ex2.approx.ftz.f32 %0, %1;" : "=f"(r) : "f"(x));
    return r;
}
__device__ __forceinline__ uint32_t f22h2(float lo, float hi) {
    uint32_t r;
    asm("cvt.rn.f16x2.f32 %0, %1, %2;" : "=r"(r) : "f"(hi), "f"(lo));
    return r;
}

// ======= fp16 tensor-core GEMM: C[M,nOut] = A[M,K] @ B^T  (A,B fp16; B stored [N,K] K-major) ===
// CTA tile BM x BN, BK=64; 8 warps; NSTG-stage cp.async ring; ldmatrix.x4 fragment loads;
// fp32 accumulate. Row stride 72 halves (144 B) -> conflict-free LDSM + STS.
// EPI: 0 = fp32 store (col guard), 1 = +bias relu -> fp16, 2 = +bias +res -> fp32,
//      3 = fp16 store (col guard)
// PERS: persistent grid, tiles pulled from *ctr (dynamic load balance).
#define SROW 72                            // halves per row (64 + 8 pad)

template <int EPI, int BM, int NSTG, int BN, int PERS>
__global__ __launch_bounds__(256,
    (BM == 64) ? 4 : (BM == 128 && BN == 64) ? 3 : (BM == 128) ? 2 : 1)
void gemm_mma(
    const __half* __restrict__ A, const __half* __restrict__ Bm, void* __restrict__ Cv,
    int K, int ldc, int nOut,
    const float* __restrict__ bias, const float* __restrict__ res,
    int* ctr, int nbx, int ntiles) {
    constexpr int MT = BM / 64;            // 16-row m-tiles per warp
    constexpr int NTW = BN / 16;           // n8-tiles per warp
    constexpr int STG = (BM + BN) * SROW;  // halves per stage
    constexpr int ACOP = BM * 8;           // A 16B copies per stage
    constexpr int CPT = (ACOP + BN * 8) / 256;

    extern __shared__ __half smem[];
    __shared__ int s_tile;
    const int tid = threadIdx.x;
    const int lane = tid & 31, w = tid >> 5;
    const int gid = lane >> 2, tig = lane & 3;
    const int warp_m = (w & 3) * (MT * 16);
    const int warp_n = (w >> 2) * (BN / 2);
    const int chunks = K >> 6;

    const int aRow = (lane & 7) + ((lane >> 3) & 1) * 8;
    const int aCol = (lane >> 4) * 8;
    const int bRow = (lane & 7) + ((lane >> 4) & 1) * 8;
    const int bCol = ((lane >> 3) & 1) * 8;

    for (;;) {
        int bx, by;
        if (PERS) {
            __syncthreads();                       // all warps done with smem + s_tile
            if (tid == 0) s_tile = atomicAdd(ctr, 1);
            __syncthreads();
            const int tile = s_tile;
            if (tile >= ntiles) return;
            bx = tile % nbx; by = tile / nbx;
        } else {
            bx = blockIdx.x; by = blockIdx.y;
        }
        const int rowBase = by * BM;
        const int colBase = bx * BN;

        float c[MT][NTW][4];
        #pragma unroll
        for (int i = 0; i < MT; i++)
            #pragma unroll
            for (int j = 0; j < NTW; j++)
                #pragma unroll
                for (int r = 0; r < 4; r++) c[i][j][r] = 0.f;

        auto load_stage = [&](int buf, int chunk) {
            __half* st = smem + buf * STG;
            const int k0 = chunk << 6;
            #pragma unroll
            for (int ii = 0; ii < CPT; ++ii) {
                const int cidx = tid + 256 * ii;
                if (cidx < ACOP) {
                    const int m = cidx >> 3, ck = cidx & 7;
                    cpasync16(st + m * SROW + ck * 8,
                              A + (size_t)(rowBase + m) * K + k0 + ck * 8);
                } else {
                    const int c2 = cidx - ACOP;
                    const int n = c2 >> 3, ck = c2 & 7;
                    cpasync16(st + BM * SROW + n * SROW + ck * 8,
                              Bm + (size_t)(colBase + n) * K + k0 + ck * 8);
                }
            }
        };

        #pragma unroll
        for (int s = 0; s < NSTG - 1; ++s) {
            if (s < chunks) load_stage(s, s);
            CP_COMMIT();
        }

        for (int j = 0; j < chunks; ++j) {
            if constexpr (NSTG == 2) asm volatile("cp.async.wait_group 0;");
            else if constexpr (NSTG == 3) asm volatile("cp.async.wait_group 1;");
            else asm volatile("cp.async.wait_group 2;");
            __syncthreads();
            const int nc = j + NSTG - 1;
            if (nc < chunks) load_stage(nc % NSTG, nc);
            CP_COMMIT();

            const __half* As = smem + (j % NSTG) * STG;
            const __half* Bs = As + BM * SROW;
            #pragma unroll
            for (int ks = 0; ks < 4; ++ks) {
                const int k0 = ks * 16;
                uint32_t a[MT][4], bb[NTW * 2];
                #pragma unroll
                for (int mt = 0; mt < MT; ++mt)
                    ldsm4(a[mt], As + (warp_m + mt * 16 + aRow) * SROW + k0 + aCol);
                #pragma unroll
                for (int np = 0; np < NTW / 2; ++np)
                    ldsm4(bb + np * 4, Bs + (warp_n + np * 16 + bRow) * SROW + k0 + bCol);
                #pragma unroll
                for (int mt = 0; mt < MT; ++mt)
                    #pragma unroll
                    for (int nt = 0; nt < NTW; ++nt)
                        mma_fp16(c[mt][nt], a[mt], bb + nt * 2);
            }
        }

        // ---------------- epilogue ----------------
        #pragma unroll
        for (int mt = 0; mt < MT; ++mt) {
            const int r0 = rowBase + warp_m + mt * 16 + gid;
            #pragma unroll
            for (int nt = 0; nt < NTW; ++nt) {
                const int col = colBase + warp_n + nt * 8 + 2 * tig;
                if (EPI == 0) {
                    float* C = (float*)Cv;
                    if (col < nOut) {
                        *(float2*)(C + (size_t)r0 * ldc + col) = make_float2(c[mt][nt][0], c[mt][nt][1]);
                        *(float2*)(C + (size_t)(r0 + 8) * ldc + col) = make_float2(c[mt][nt][2], c[mt][nt][3]);
                    }
                } else if (EPI == 1) {
                    __half* C = (__half*)Cv;
                    float2 bv = *(const float2*)(bias + col);
                    __half2 v0 = __floats2half2_rn(fmaxf(c[mt][nt][0] + bv.x, 0.f),
                                                   fmaxf(c[mt][nt][1] + bv.y, 0.f));
                    __half2 v1 = __floats2half2_rn(fmaxf(c[mt][nt][2] + bv.x, 0.f),
                                                   fmaxf(c[mt][nt][3] + bv.y, 0.f));
                    *(__half2*)(C + (size_t)r0 * ldc + col) = v0;
                    *(__half2*)(C + (size_t)(r0 + 8) * ldc + col) = v1;
                } else if (EPI == 2) {
                    float* C = (float*)Cv;
                    float2 bv = *(const float2*)(bias + col);
                    float2 rv0 = *(const float2*)(res + (size_t)r0 * ldc + col);
                    float2 rv1 = *(const float2*)(res + (size_t)(r0 + 8) * ldc + col);
                    float2 v0, v1;
                    v0.x = c[mt][nt][0] + bv.x + rv0.x;
                    v0.y = c[mt][nt][1] + bv.y + rv0.y;
                    v1.x = c[mt][nt][2] + bv.x + rv1.x;
                    v1.y = c[mt][nt][3] + bv.y + rv1.y;
                    *(float2*)(C + (size_t)r0 * ldc + col) = v0;
                    *(float2*)(C + (size_t)(r0 + 8) * ldc + col) = v1;
                } else {
                    __half* C = (__half*)Cv;
                    if (col < nOut) {
                        *(__half2*)(C + (size_t)r0 * ldc + col) =
                            __floats2half2_rn(c[mt][nt][0], c[mt][nt][1]);
                        *(__half2*)(C + (size_t)(r0 + 8) * ldc + col) =
                            __floats2half2_rn(c[mt][nt][2], c[mt][nt][3]);
                    }
                }
            }
        }
        if (!PERS) return;
    }
}

// ---------------- LayerNorm row body (fp16 output), 256 threads ----------------
__device__ __forceinline__ void ln_row(
    const float* __restrict__ in, const float* __restrict__ g,
    const float* __restrict__ b, __half* __restrict__ out, int row,
    float* red0, float* red1) {
    const float* x = in + (size_t)row * D_;
    float s = 0.f, ss = 0.f;
    for (int i = threadIdx.x; i < D_; i += 256) {
        float v = x[i];
        s += v; ss += v * v;
    }
    #pragma unroll
    for (int o = 16; o; o >>= 1) {
        s  += __shfl_xor_sync(0xffffffffu, s, o);
        ss += __shfl_xor_sync(0xffffffffu, ss, o);
    }
    int w = threadIdx.x >> 5, l = threadIdx.x & 31;
    if (l == 0) { red0[w] = s; red1[w] = ss; }
    __syncthreads();
    if (w == 0) {
        s  = (l < 8) ? red0[l] : 0.f;
        ss = (l < 8) ? red1[l] : 0.f;
        #pragma unroll
        for (int o = 4; o; o >>= 1) {
            s  += __shfl_xor_sync(0xffffffffu, s, o);
            ss += __shfl_xor_sync(0xffffffffu, ss, o);
        }
        if (l == 0) { red0[0] = s; red1[0] = ss; }
    }
    __syncthreads();
    float mean = red0[0] * (1.f / D_);
    float var  = red1[0] * (1.f / D_) - mean * mean;
    float inv  = rsqrtf(var + EPS_);
    __half* o = out + (size_t)row * D_;
    for (int i = threadIdx.x; i < D_; i += 256)
        o[i] = __float2half_rn((x[i] - mean) * inv * g[i] + b[i]);
}

__global__ __launch_bounds__(256) void layernorm_kernel(
    const float* __restrict__ in, const float* __restrict__ g,
    const float* __restrict__ b, __half* __restrict__ out) {
    __shared__ float red0[8], red1[8];
    ln_row(in, g, b, out, blockIdx.x, red0, red1);
}

// ------- fused prep: ctr reset, W1^T, W2^T, QKV pack, Wo pack, g_o pad-zero, LN1 -------
__device__ __forceinline__ void transpose_dev(
    const float* __restrict__ src, __half* __restrict__ dst,
    int R, int C, int bx, int by, float (*tile)[33]) {
    const int tx = threadIdx.x & 31, ty = threadIdx.x >> 5;   // 32 x 8
    const int x = bx * 32 + tx;
    const int y0 = by * 32;
    #pragma unroll
    for (int j = 0; j < 4; ++j)
        tile[ty + j * 8][tx] = src[(size_t)(y0 + ty + j * 8) * C + x];
    __syncthreads();
    const int x2 = by * 32 + tx;
    const int y2 = bx * 32;
    #pragma unroll
    for (int j = 0; j < 4; ++j)
        dst[(size_t)(y2 + ty + j * 8) * R + x2] = __float2half_rn(tile[tx][ty + j * 8]);
}

#define NB_W1 2304   // (3072/32) * (768/32)
#define NB_W2 2304
#define NB_QK 768    // 256*768 / 256
#define NB_WO 384    // 768*128 / 256
#define NB_PAD 448   // 16384 rows * 7 uint4 / 256
#define NB_FIX (NB_W1 + NB_W2 + NB_QK + NB_WO + NB_PAD)

__global__ __launch_bounds__(256) void prep_kernel(
    const float* __restrict__ Wq, const float* __restrict__ Wk, const float* __restrict__ Wv,
    const float* __restrict__ Wo, const float* __restrict__ W1, const float* __restrict__ W2,
    const float* __restrict__ x, const float* __restrict__ g1, const float* __restrict__ beta1) {
    __shared__ float tile[32][33];
    __shared__ float red0[8], red1[8];
    const int bid = blockIdx.x;
    if (bid == 0 && threadIdx.x == 0) { g_ctr1 = 0; g_ctr2 = 0; }
    if (bid < NB_W1) {
        transpose_dev(W1, g_b1t, D_, DFF_, bid % (DFF_ / 32), bid / (DFF_ / 32), tile);
    } else if (bid < NB_W1 + NB_W2) {
        const int b2 = bid - NB_W1;
        transpose_dev(W2, g_b2t, DFF_, D_, b2 % (D_ / 32), b2 / (D_ / 32), tile);
    } else if (bid < NB_W1 + NB_W2 + NB_QK) {
        const int i = (bid - NB_W1 - NB_W2) * 256 + threadIdx.x;
        const int n = i / D_, k = i % D_;
        float v = 0.f;
        if (n < QKVN_) {
            const int which = n / HE_, he = n % HE_;
            const int h = he / E_, e = he % E_;
            const float* src = (which == 0) ? Wq : (which == 1) ? Wk : Wv;
            v = src[((size_t)h * D_ + k) * E_ + e];
        }
        g_bqkvt[i] = __float2half_rn(v);
    } else if (bid < NB_W1 + NB_W2 + NB_QK + NB_WO) {
        const int i = (bid - NB_W1 - NB_W2 - NB_QK) * 256 + threadIdx.x;
        const int n = i / KPAD_, k = i % KPAD_;
        const float v = (k < HE_) ? Wo[(size_t)k * D_ + n] : 0.f;
        g_bot[i] = __float2half_rn(v);
    } else if (bid < NB_FIX) {
        // zero g_o pad columns [72,128): 7 uint4 per row
        const int i = (bid - NB_W1 - NB_W2 - NB_QK - NB_WO) * 256 + threadIdx.x;
        const int row = i / 7, c = i % 7;
        *(uint4*)(g_o + (size_t)row * KPAD_ + HE_ + c * 8) = make_uint4(0, 0, 0, 0);
    } else {
        ln_row(x, g1, beta1, g_xn, bid - NB_FIX, red0, red1);
    }
}

// ---------------- tensor-core causal attention (flash-style, no-max softmax) ----------------
// Grid (qb, h, b): CTA owns 128 queries of (b,h). 8 warps x 16 query rows. qkv is fp16.
__global__ __launch_bounds__(256) void attention_tc() {
    const int qb = blockIdx.x;
    const int h  = blockIdx.y;
    const int b  = blockIdx.z;
    __shared__ __half Qs[128 * 24];   // stride 24 halves: conflict-free ldmatrix
    __shared__ __half Ks[64 * 24];
    __shared__ __half Vts[16 * SROW]; // V transposed [e][key], ones at e=6
    const int tid = threadIdx.x;
    const int lane = tid & 31, w = tid >> 5;
    const int gid = lane >> 2, tig = lane & 3;
    const __half* base = g_qkv + (size_t)b * T_ * QKVN_;
    const int qbase = qb * 128;
    const float scale2 = 0.4082482904638631f * 1.4426950408889634f; // 1/sqrt(6)*log2(e)

    for (int i = tid; i < 128 * 16; i += 256) {
        const int r = i >> 4, e = i & 15;
        const float v = (e < E_) ? __half2float(base[(qbase + r) * QKVN_ + h * E_ + e]) * scale2
                                 : 0.f;
        Qs[r * 24 + e] = __float2half_rn(v);
    }
    __syncthreads();

    const int aRow = (lane & 7) + ((lane >> 3) & 1) * 8;
    const int aCol = (lane >> 4) * 8;
    const int bRow = (lane & 7) + ((lane >> 4) & 1) * 8;
    const int bCol = ((lane >> 3) & 1) * 8;

    uint32_t qa[4];
    ldsm4(qa, Qs + (w * 16 + aRow) * 24 + aCol);   // Q fragment, lives all kernel

    float co[4] = {0.f, 0.f, 0.f, 0.f};            // O accum: e0..5, l at col 6
    const int rowg0 = qbase + w * 16 + gid;
    const int rowg1 = rowg0 + 8;

    const int nchunks = 2 * qb + 2;
    for (int c = 0; c < nchunks; ++c) {
        __syncthreads();
        const int cbase = c * 64;
        for (int i = tid; i < 64 * 16; i += 256) {
            const int s = i >> 4, e = i & 15;
            Ks[s * 24 + e] = (e < E_) ? base[(cbase + s) * QKVN_ + HE_ + h * E_ + e]
                                      : __ushort_as_half(0);
        }
        for (int i = tid; i < 16 * 64; i += 256) {
            const int e = i >> 6, s = i & 63;
            __half v;
            if (e < E_)      v = base[(cbase + s) * QKVN_ + 2 * HE_ + h * E_ + e];
            else if (e == E_) v = __float2half_rn(1.f);
            else              v = __ushort_as_half(0);
            Vts[e * SROW + s] = v;
        }
        __syncthreads();

        float sc[8][4];
        #pragma unroll
        for (int nt = 0; nt < 8; ++nt)
            #pragma unroll
            for (int j = 0; j < 4; ++j) sc[nt][j] = 0.f;
        uint32_t kb[16];
        #pragma unroll
        for (int np = 0; np < 4; ++np)
            ldsm4(kb + np * 4, Ks + (np * 16 + bRow) * 24 + bCol);
        #pragma unroll
        for (int nt = 0; nt < 8; ++nt)
            mma_fp16(sc[nt], qa, kb + ((nt >> 1) * 4 + (nt & 1) * 2));

        if (c >= 2 * qb) {
            #pragma unroll
            for (int nt = 0; nt < 8; ++nt) {
                const int colb = cbase + nt * 8 + 2 * tig;
                sc[nt][0] = (colb     <= rowg0) ? ex2f(sc[nt][0]) : 0.f;
                sc[nt][1] = (colb + 1 <= rowg0) ? ex2f(sc[nt][1]) : 0.f;
                sc[nt][2] = (colb     <= rowg1) ? ex2f(sc[nt][2]) : 0.f;
                sc[nt][3] = (colb + 1 <= rowg1) ? ex2f(sc[nt][3]) : 0.f;
            }
        } else {
            #pragma unroll
            for (int nt = 0; nt < 8; ++nt)
                #pragma unroll
                for (int j = 0; j < 4; ++j) sc[nt][j] = ex2f(sc[nt][j]);
        }

        #pragma unroll
        for (int ks = 0; ks < 4; ++ks) {
            uint32_t pa[4];
            pa[0] = f22h2(sc[2 * ks][0],     sc[2 * ks][1]);
            pa[1] = f22h2(sc[2 * ks][2],     sc[2 * ks][3]);
            pa[2] = f22h2(sc[2 * ks + 1][0], sc[2 * ks + 1][1]);
            pa[3] = f22h2(sc[2 * ks + 1][2], sc[2 * ks + 1][3]);
            uint32_t vb[4];
            ldsm4(vb, Vts + bRow * SROW + ks * 16 + bCol);
            mma_fp16(co, pa, vb);
        }
    }

    const float linv0 = 1.f / __shfl_sync(0xffffffffu, co[0], lane | 3);
    const float linv1 = 1.f / __shfl_sync(0xffffffffu, co[2], lane | 3);
    if (tig < 3) {
        *(__half2*)(g_o + ((size_t)b * T_ + rowg0) * KPAD_ + h * E_ + 2 * tig) =
            __floats2half2_rn(co[0] * linv0, co[1] * linv0);
        *(__half2*)(g_o + ((size_t)b * T_ + rowg1) * KPAD_ + h * E_ + 2 * tig) =
            __floats2half2_rn(co[2] * linv1, co[3] * linv1);
    }
}

// ---------------- launch ----------------
extern "C" void kernel_launch(void* const* d_in, const int* in_sizes, int n_in,
                              void* d_out, int out_size) {
    const float* x     = (const float*)d_in[0];
    const float* Wq    = (const float*)d_in[1];
    const float* Wk    = (const float*)d_in[2];
    const float* Wv    = (const float*)d_in[3];
    const float* Wo    = (const float*)d_in[4];
    const float* bo    = (const float*)d_in[5];
    const float* W1    = (const float*)d_in[6];
    const float* b1    = (const float*)d_in[7];
    const float* W2    = (const float*)d_in[8];
    const float* b2    = (const float*)d_in[9];
    const float* g1    = (const float*)d_in[10];
    const float* beta1 = (const float*)d_in[11];
    const float* g2    = (const float*)d_in[12];
    const float* beta2 = (const float*)d_in[13];
    float* out = (float*)d_out;

    __half *xn, *qkv, *o, *hb, *bqkvt, *bot, *b1t, *b2t;
    float *x2;
    int *ctr1, *ctr2;
    cudaGetSymbolAddress((void**)&xn,    g_xn);
    cudaGetSymbolAddress((void**)&qkv,   g_qkv);
    cudaGetSymbolAddress((void**)&o,     g_o);
    cudaGetSymbolAddress((void**)&x2,    g_x2);
    cudaGetSymbolAddress((void**)&hb,    g_h);
    cudaGetSymbolAddress((void**)&bqkvt, g_bqkvt);
    cudaGetSymbolAddress((void**)&bot,   g_bot);
    cudaGetSymbolAddress((void**)&b1t,   g_b1t);
    cudaGetSymbolAddress((void**)&b2t,   g_b2t);
    cudaGetSymbolAddress((void**)&ctr1,  g_ctr1);
    cudaGetSymbolAddress((void**)&ctr2,  g_ctr2);

    const int SM_BIG = 4 * (256 + 128) * SROW * 2;   // 221184 B
    const int SM_QKV = 3 * (128 + 128) * SROW * 2;   // 110592 B
    const int SM_PRJ = 2 * (64 + 128) * SROW * 2;    //  55296 B
    cudaFuncSetAttribute(gemm_mma<3, 128, 3, 128, 0>, cudaFuncAttributeMaxDynamicSharedMemorySize, SM_QKV);
    cudaFuncSetAttribute(gemm_mma<2, 64, 2, 128, 0>,  cudaFuncAttributeMaxDynamicSharedMemorySize, SM_PRJ);
    cudaFuncSetAttribute(gemm_mma<1, 256, 4, 128, 1>, cudaFuncAttributeMaxDynamicSharedMemorySize, SM_BIG);
    cudaFuncSetAttribute(gemm_mma<2, 256, 4, 128, 1>, cudaFuncAttributeMaxDynamicSharedMemorySize, SM_BIG);

    // fused prep: counter reset + weight packs + g_o pad zero + LN1 (single launch)
    prep_kernel<<<NB_FIX + M_, 256>>>(Wq, Wk, Wv, Wo, W1, W2, x, g1, beta1);

    // QKV: [16384, 216(pad 256), K=768] -> fp16 qkv
    gemm_mma<3, 128, 3, 128, 0><<<dim3(2, M_ / 128), 256, SM_QKV>>>(
        xn, bqkvt, qkv, D_, QKVN_, QKVN_, nullptr, nullptr, nullptr, 0, 0);
    // attention (tensor-core flash-style) -> g_o [M, 128] fp16
    attention_tc<<<dim3(T_ / 128, H_, B_), 256>>>();
    // proj + bias + residual: x2 = x + o @ Wo + bo   [16384, 768, K=128]
    gemm_mma<2, 64, 2, 128, 0><<<dim3(D_ / 128, M_ / 64), 256, SM_PRJ>>>(
        o, bot, x2, KPAD_, D_, D_, bo, x, nullptr, 0, 0);
    // LN2 -> xn (fp16)
    layernorm_kernel<<<M_, 256>>>(x2, g2, beta2, xn);
    // FFN1: h = relu(y @ W1 + b1) -> fp16   [16384, 3072, K=768]  (persistent, dynamic tiles)
    gemm_mma<1, 256, 4, 128, 1><<<148, 256, SM_BIG>>>(
        xn, b1t, hb, D_, DFF_, DFF_, b1, nullptr, ctr1, DFF_ / 128, (DFF_ / 128) * (M_ / 256));
    // FFN2: out = x2 + h @ W2 + b2   [16384, 768, K=3072]  (persistent, dynamic tiles)
    gemm_mma<2, 256, 4, 128, 1><<<148, 256, SM_BIG>>>(
        hb, b2t, out, DFF_, D_, D_, b2, x2, ctr2, D_ / 128, (D_ / 128) * (M_ / 256));
}

// round 16
// speedup vs baseline: 1.0478x; 1.0478x over previous
#include <cuda_runtime.h>
#include <cuda_fp16.h>
#include <cstdint>
#include <math.h>

// ---------------- problem constants ----------------
#define B_  32
#define T_  512
#define D_  768
#define H_  12
#define E_  6
#define HE_ 72
#define QKVN_ 216
#define DFF_ 3072
#define M_  (B_ * T_)        // 16384
#define EPS_ 1e-5f
#define KPAD_ 128            // proj K padded 72 -> 128 (divisible by BK=64)

// ---------------- scratch (device globals) ----------------
__device__ __half g_xn [M_ * D_];          // LN output (fp16)
__device__ __half g_qkv[M_ * QKVN_];       // q|k|v per row (fp16)
__device__ __half g_o  [M_ * KPAD_];       // attention out, padded to 128 cols (fp16)
__device__ float  g_x2 [M_ * D_];          // residual 1 (fp32)
__device__ __half g_h  [M_ * DFF_];        // FFN hidden (fp16)
__device__ __half g_bqkvt[256 * D_];       // QKV weights [256(n pad), 768] fp16 K-major
__device__ __half g_bot[D_ * KPAD_];       // Wo^T [768, 128] fp16 (K padded)
__device__ __half g_b1t[DFF_ * D_];        // W1^T [3072, 768] fp16
__device__ __half g_b2t[D_ * DFF_];        // W2^T [768, 3072] fp16
__device__ int    g_ctr1, g_ctr2;          // dynamic tile counters (reset each launch in prep)

// ---------------- helpers ----------------
__device__ __forceinline__ void cpasync16(void* dst, const void* src) {
    uint32_t d;
    asm("{ .reg .u64 t; cvta.to.shared.u64 t, %1; cvt.u32.u64 %0, t; }" : "=r"(d) : "l"(dst));
    asm volatile("cp.async.cg.shared.global [%0], [%1], 16;" :: "r"(d), "l"(src));
}
#define CP_COMMIT() asm volatile("cp.async.commit_group;")

__device__ __forceinline__ void mma_fp16(float* c, const uint32_t* a, const uint32_t* b) {
    asm volatile(
        "mma.sync.aligned.m16n8k16.row.col.f32.f16.f16.f32 "
        "{%0,%1,%2,%3}, {%4,%5,%6,%7}, {%8,%9}, {%0,%1,%2,%3};"
        : "+f"(c[0]), "+f"(c[1]), "+f"(c[2]), "+f"(c[3])
        : "r"(a[0]), "r"(a[1]), "r"(a[2]), "r"(a[3]), "r"(b[0]), "r"(b[1]));
}
__device__ __forceinline__ void ldsm4(uint32_t* r, const __half* p) {
    uint32_t a;
    asm("{ .reg .u64 t; cvta.to.shared.u64 t, %1; cvt.u32.u64 %0, t; }" : "=r"(a) : "l"(p));
    asm volatile("ldmatrix.sync.aligned.m8n8.x4.shared.b16 {%0,%1,%2,%3}, [%4];"
        : "=r"(r[0]), "=r"(r[1]), "=r"(r[2]), "=r"(r[3]) : "r"(a));
}
__device__ __forceinline__ float ex2f(float x) {
    float r;
    asm("ex2.approx.ftz.f32 %0, %1;" : "=f"(r) : "f"(x));
    return r;
}
__device__ __forceinline__ uint32_t f22h2(float lo, float hi) {
    uint32_t r;
    asm("cvt.rn.f16x2.f32 %0, %1, %2;" : "=r"(r) : "f"(hi), "f"(lo));
    return r;
}

// ======= fp16 tensor-core GEMM: C[M,nOut] = A[M,K] @ B^T  (A,B fp16; B stored [N,K] K-major) ===
// CTA tile BM x BN, BK=64; 8 warps; NSTG-stage cp.async ring; ldmatrix.x4 fragment loads;
// fp32 accumulate. Row stride 72 halves (144 B) -> conflict-free LDSM + STS.
// EPI: 0 = fp32 store (col guard), 1 = +bias relu -> fp16, 2 = +bias +res -> fp32,
//      3 = fp16 store (col guard)
// PERS: persistent grid, tiles pulled from *ctr (dynamic load balance).
#define SROW 72                            // halves per row (64 + 8 pad)

template <int EPI, int BM, int NSTG, int BN, int PERS>
__global__ __launch_bounds__(256,
    (BM == 64) ? 4 : (BM == 128 && BN == 64) ? 3 : (BM == 128) ? 2 : 1)
void gemm_mma(
    const __half* __restrict__ A, const __half* __restrict__ Bm, void* __restrict__ Cv,
    int K, int ldc, int nOut,
    const float* __restrict__ bias, const float* __restrict__ res,
    int* ctr, int nbx, int ntiles) {
    constexpr int MT = BM / 64;            // 16-row m-tiles per warp
    constexpr int NTW = BN / 16;           // n8-tiles per warp
    constexpr int STG = (BM + BN) * SROW;  // halves per stage
    constexpr int ACOP = BM * 8;           // A 16B copies per stage
    constexpr int CPT = (ACOP + BN * 8) / 256;

    extern __shared__ __half smem[];
    __shared__ int s_tile;
    const int tid = threadIdx.x;
    const int lane = tid & 31, w = tid >> 5;
    const int gid = lane >> 2, tig = lane & 3;
    const int warp_m = (w & 3) * (MT * 16);
    const int warp_n = (w >> 2) * (BN / 2);
    const int chunks = K >> 6;

    const int aRow = (lane & 7) + ((lane >> 3) & 1) * 8;
    const int aCol = (lane >> 4) * 8;
    const int bRow = (lane & 7) + ((lane >> 4) & 1) * 8;
    const int bCol = ((lane >> 3) & 1) * 8;

    for (;;) {
        int bx, by;
        if (PERS) {
            __syncthreads();                       // all warps done with smem + s_tile
            if (tid == 0) s_tile = atomicAdd(ctr, 1);
            __syncthreads();
            const int tile = s_tile;
            if (tile >= ntiles) return;
            bx = tile % nbx; by = tile / nbx;
        } else {
            bx = blockIdx.x; by = blockIdx.y;
        }
        const int rowBase = by * BM;
        const int colBase = bx * BN;

        float c[MT][NTW][4];
        #pragma unroll
        for (int i = 0; i < MT; i++)
            #pragma unroll
            for (int j = 0; j < NTW; j++)
                #pragma unroll
                for (int r = 0; r < 4; r++) c[i][j][r] = 0.f;

        auto load_stage = [&](int buf, int chunk) {
            __half* st = smem + buf * STG;
            const int k0 = chunk << 6;
            #pragma unroll
            for (int ii = 0; ii < CPT; ++ii) {
                const int cidx = tid + 256 * ii;
                if (cidx < ACOP) {
                    const int m = cidx >> 3, ck = cidx & 7;
                    cpasync16(st + m * SROW + ck * 8,
                              A + (size_t)(rowBase + m) * K + k0 + ck * 8);
                } else {
                    const int c2 = cidx - ACOP;
                    const int n = c2 >> 3, ck = c2 & 7;
                    cpasync16(st + BM * SROW + n * SROW + ck * 8,
                              Bm + (size_t)(colBase + n) * K + k0 + ck * 8);
                }
            }
        };

        #pragma unroll
        for (int s = 0; s < NSTG - 1; ++s) {
            if (s < chunks) load_stage(s, s);
            CP_COMMIT();
        }

        for (int j = 0; j < chunks; ++j) {
            if constexpr (NSTG == 2) asm volatile("cp.async.wait_group 0;");
            else if constexpr (NSTG == 3) asm volatile("cp.async.wait_group 1;");
            else asm volatile("cp.async.wait_group 2;");
            __syncthreads();
            const int nc = j + NSTG - 1;
            if (nc < chunks) load_stage(nc % NSTG, nc);
            CP_COMMIT();

            const __half* As = smem + (j % NSTG) * STG;
            const __half* Bs = As + BM * SROW;
            #pragma unroll
            for (int ks = 0; ks < 4; ++ks) {
                const int k0 = ks * 16;
                uint32_t a[MT][4], bb[NTW * 2];
                #pragma unroll
                for (int mt = 0; mt < MT; ++mt)
                    ldsm4(a[mt], As + (warp_m + mt * 16 + aRow) * SROW + k0 + aCol);
                #pragma unroll
                for (int np = 0; np < NTW / 2; ++np)
                    ldsm4(bb + np * 4, Bs + (warp_n + np * 16 + bRow) * SROW + k0 + bCol);
                #pragma unroll
                for (int mt = 0; mt < MT; ++mt)
                    #pragma unroll
                    for (int nt = 0; nt < NTW; ++nt)
                        mma_fp16(c[mt][nt], a[mt], bb + nt * 2);
            }
        }

        // ---------------- epilogue ----------------
        #pragma unroll
        for (int mt = 0; mt < MT; ++mt) {
            const int r0 = rowBase + warp_m + mt * 16 + gid;
            #pragma unroll
            for (int nt = 0; nt < NTW; ++nt) {
                const int col = colBase + warp_n + nt * 8 + 2 * tig;
                if (EPI == 0) {
                    float* C = (float*)Cv;
                    if (col < nOut) {
                        *(float2*)(C + (size_t)r0 * ldc + col) = make_float2(c[mt][nt][0], c[mt][nt][1]);
                        *(float2*)(C + (size_t)(r0 + 8) * ldc + col) = make_float2(c[mt][nt][2], c[mt][nt][3]);
                    }
                } else if (EPI == 1) {
                    __half* C = (__half*)Cv;
                    float2 bv = *(const float2*)(bias + col);
                    __half2 v0 = __floats2half2_rn(fmaxf(c[mt][nt][0] + bv.x, 0.f),
                                                   fmaxf(c[mt][nt][1] + bv.y, 0.f));
                    __half2 v1 = __floats2half2_rn(fmaxf(c[mt][nt][2] + bv.x, 0.f),
                                                   fmaxf(c[mt][nt][3] + bv.y, 0.f));
                    *(__half2*)(C + (size_t)r0 * ldc + col) = v0;
                    *(__half2*)(C + (size_t)(r0 + 8) * ldc + col) = v1;
                } else if (EPI == 2) {
                    float* C = (float*)Cv;
                    float2 bv = *(const float2*)(bias + col);
                    float2 rv0 = *(const float2*)(res + (size_t)r0 * ldc + col);
                    float2 rv1 = *(const float2*)(res + (size_t)(r0 + 8) * ldc + col);
                    float2 v0, v1;
                    v0.x = c[mt][nt][0] + bv.x + rv0.x;
                    v0.y = c[mt][nt][1] + bv.y + rv0.y;
                    v1.x = c[mt][nt][2] + bv.x + rv1.x;
                    v1.y = c[mt][nt][3] + bv.y + rv1.y;
                    *(float2*)(C + (size_t)r0 * ldc + col) = v0;
                    *(float2*)(C + (size_t)(r0 + 8) * ldc + col) = v1;
                } else {
                    __half* C = (__half*)Cv;
                    if (col < nOut) {
                        *(__half2*)(C + (size_t)r0 * ldc + col) =
                            __floats2half2_rn(c[mt][nt][0], c[mt][nt][1]);
                        *(__half2*)(C + (size_t)(r0 + 8) * ldc + col) =
                            __floats2half2_rn(c[mt][nt][2], c[mt][nt][3]);
                    }
                }
            }
        }
        if (!PERS) return;
    }
}

// ---------------- LayerNorm row body (fp16 output), 256 threads ----------------
__device__ __forceinline__ void ln_row(
    const float* __restrict__ in, const float* __restrict__ g,
    const float* __restrict__ b, __half* __restrict__ out, int row,
    float* red0, float* red1) {
    const float* x = in + (size_t)row * D_;
    float s = 0.f, ss = 0.f;
    for (int i = threadIdx.x; i < D_; i += 256) {
        float v = x[i];
        s += v; ss += v * v;
    }
    #pragma unroll
    for (int o = 16; o; o >>= 1) {
        s  += __shfl_xor_sync(0xffffffffu, s, o);
        ss += __shfl_xor_sync(0xffffffffu, ss, o);
    }
    int w = threadIdx.x >> 5, l = threadIdx.x & 31;
    if (l == 0) { red0[w] = s; red1[w] = ss; }
    __syncthreads();
    if (w == 0) {
        s  = (l < 8) ? red0[l] : 0.f;
        ss = (l < 8) ? red1[l] : 0.f;
        #pragma unroll
        for (int o = 4; o; o >>= 1) {
            s  += __shfl_xor_sync(0xffffffffu, s, o);
            ss += __shfl_xor_sync(0xffffffffu, ss, o);
        }
        if (l == 0) { red0[0] = s; red1[0] = ss; }
    }
    __syncthreads();
    float mean = red0[0] * (1.f / D_);
    float var  = red1[0] * (1.f / D_) - mean * mean;
    float inv  = rsqrtf(var + EPS_);
    __half* o = out + (size_t)row * D_;
    for (int i = threadIdx.x; i < D_; i += 256)
        o[i] = __float2half_rn((x[i] - mean) * inv * g[i] + b[i]);
}

__global__ __launch_bounds__(256) void layernorm_kernel(
    const float* __restrict__ in, const float* __restrict__ g,
    const float* __restrict__ b, __half* __restrict__ out) {
    __shared__ float red0[8], red1[8];
    ln_row(in, g, b, out, blockIdx.x, red0, red1);
}

// ------- fused prep: ctr reset, W1^T, W2^T, QKV pack, Wo pack, g_o pad-zero, LN1 -------
__device__ __forceinline__ void transpose_dev(
    const float* __restrict__ src, __half* __restrict__ dst,
    int R, int C, int bx, int by, float (*tile)[33]) {
    const int tx = threadIdx.x & 31, ty = threadIdx.x >> 5;   // 32 x 8
    const int x = bx * 32 + tx;
    const int y0 = by * 32;
    #pragma unroll
    for (int j = 0; j < 4; ++j)
        tile[ty + j * 8][tx] = src[(size_t)(y0 + ty + j * 8) * C + x];
    __syncthreads();
    const int x2 = by * 32 + tx;
    const int y2 = bx * 32;
    #pragma unroll
    for (int j = 0; j < 4; ++j)
        dst[(size_t)(y2 + ty + j * 8) * R + x2] = __float2half_rn(tile[tx][ty + j * 8]);
}

#define NB_W1 2304   // (3072/32) * (768/32)
#define NB_W2 2304
#define NB_QK 768    // 256*768 / 256
#define NB_WO 384    // 768*128 / 256
#define NB_PAD 448   // 16384 rows * 7 uint4 / 256
#define NB_FIX (NB_W1 + NB_W2 + NB_QK + NB_WO + NB_PAD)

__global__ __launch_bounds__(256) void prep_kernel(
    const float* __restrict__ Wq, const float* __restrict__ Wk, const float* __restrict__ Wv,
    const float* __restrict__ Wo, const float* __restrict__ W1, const float* __restrict__ W2,
    const float* __restrict__ x, const float* __restrict__ g1, const float* __restrict__ beta1) {
    __shared__ float tile[32][33];
    __shared__ float red0[8], red1[8];
    const int bid = blockIdx.x;
    if (bid == 0 && threadIdx.x == 0) { g_ctr1 = 0; g_ctr2 = 0; }
    if (bid < NB_W1) {
        transpose_dev(W1, g_b1t, D_, DFF_, bid % (DFF_ / 32), bid / (DFF_ / 32), tile);
    } else if (bid < NB_W1 + NB_W2) {
        const int b2 = bid - NB_W1;
        transpose_dev(W2, g_b2t, DFF_, D_, b2 % (D_ / 32), b2 / (D_ / 32), tile);
    } else if (bid < NB_W1 + NB_W2 + NB_QK) {
        const int i = (bid - NB_W1 - NB_W2) * 256 + threadIdx.x;
        const int n = i / D_, k = i % D_;
        float v = 0.f;
        if (n < QKVN_) {
            const int which = n / HE_, he = n % HE_;
            const int h = he / E_, e = he % E_;
            const float* src = (which == 0) ? Wq : (which == 1) ? Wk : Wv;
            v = src[((size_t)h * D_ + k) * E_ + e];
        }
        g_bqkvt[i] = __float2half_rn(v);
    } else if (bid < NB_W1 + NB_W2 + NB_QK + NB_WO) {
        const int i = (bid - NB_W1 - NB_W2 - NB_QK) * 256 + threadIdx.x;
        const int n = i / KPAD_, k = i % KPAD_;
        const float v = (k < HE_) ? Wo[(size_t)k * D_ + n] : 0.f;
        g_bot[i] = __float2half_rn(v);
    } else if (bid < NB_FIX) {
        // zero g_o pad columns [72,128): 7 uint4 per row
        const int i = (bid - NB_W1 - NB_W2 - NB_QK - NB_WO) * 256 + threadIdx.x;
        const int row = i / 7, c = i % 7;
        *(uint4*)(g_o + (size_t)row * KPAD_ + HE_ + c * 8) = make_uint4(0, 0, 0, 0);
    } else {
        ln_row(x, g1, beta1, g_xn, bid - NB_FIX, red0, red1);
    }
}

// ---------------- tensor-core causal attention (flash-style, no-max softmax) ----------------
// Grid (qb, h, b): CTA owns 128 queries of (b,h). 8 warps x 16 query rows. qkv is fp16.
__global__ __launch_bounds__(256) void attention_tc() {
    const int qb = blockIdx.x;
    const int h  = blockIdx.y;
    const int b  = blockIdx.z;
    __shared__ __half Qs[128 * 24];   // stride 24 halves: conflict-free ldmatrix
    __shared__ __half Ks[64 * 24];
    __shared__ __half Vts[16 * SROW]; // V transposed [e][key], ones at e=6
    const int tid = threadIdx.x;
    const int lane = tid & 31, w = tid >> 5;
    const int gid = lane >> 2, tig = lane & 3;
    const __half* base = g_qkv + (size_t)b * T_ * QKVN_;
    const int qbase = qb * 128;
    const float scale2 = 0.4082482904638631f * 1.4426950408889634f; // 1/sqrt(6)*log2(e)

    for (int i = tid; i < 128 * 16; i += 256) {
        const int r = i >> 4, e = i & 15;
        const float v = (e < E_) ? __half2float(base[(qbase + r) * QKVN_ + h * E_ + e]) * scale2
                                 : 0.f;
        Qs[r * 24 + e] = __float2half_rn(v);
    }
    __syncthreads();

    const int aRow = (lane & 7) + ((lane >> 3) & 1) * 8;
    const int aCol = (lane >> 4) * 8;
    const int bRow = (lane & 7) + ((lane >> 4) & 1) * 8;
    const int bCol = ((lane >> 3) & 1) * 8;

    uint32_t qa[4];
    ldsm4(qa, Qs + (w * 16 + aRow) * 24 + aCol);   // Q fragment, lives all kernel

    float co[4] = {0.f, 0.f, 0.f, 0.f};            // O accum: e0..5, l at col 6
    const int rowg0 = qbase + w * 16 + gid;
    const int rowg1 = rowg0 + 8;

    const int nchunks = 2 * qb + 2;
    for (int c = 0; c < nchunks; ++c) {
        __syncthreads();
        const int cbase = c * 64;
        for (int i = tid; i < 64 * 16; i += 256) {
            const int s = i >> 4, e = i & 15;
            Ks[s * 24 + e] = (e < E_) ? base[(cbase + s) * QKVN_ + HE_ + h * E_ + e]
                                      : __ushort_as_half(0);
        }
        for (int i = tid; i < 16 * 64; i += 256) {
            const int e = i >> 6, s = i & 63;
            __half v;
            if (e < E_)      v = base[(cbase + s) * QKVN_ + 2 * HE_ + h * E_ + e];
            else if (e == E_) v = __float2half_rn(1.f);
            else              v = __ushort_as_half(0);
            Vts[e * SROW + s] = v;
        }
        __syncthreads();

        float sc[8][4];
        #pragma unroll
        for (int nt = 0; nt < 8; ++nt)
            #pragma unroll
            for (int j = 0; j < 4; ++j) sc[nt][j] = 0.f;
        uint32_t kb[16];
        #pragma unroll
        for (int np = 0; np < 4; ++np)
            ldsm4(kb + np * 4, Ks + (np * 16 + bRow) * 24 + bCol);
        #pragma unroll
        for (int nt = 0; nt < 8; ++nt)
            mma_fp16(sc[nt], qa, kb + ((nt >> 1) * 4 + (nt & 1) * 2));

        if (c >= 2 * qb) {
            #pragma unroll
            for (int nt = 0; nt < 8; ++nt) {
                const int colb = cbase + nt * 8 + 2 * tig;
                sc[nt][0] = (colb     <= rowg0) ? ex2f(sc[nt][0]) : 0.f;
                sc[nt][1] = (colb + 1 <= rowg0) ? ex2f(sc[nt][1]) : 0.f;
                sc[nt][2] = (colb     <= rowg1) ? ex2f(sc[nt][2]) : 0.f;
                sc[nt][3] = (colb + 1 <= rowg1) ? ex2f(sc[nt][3]) : 0.f;
            }
        } else {
            #pragma unroll
            for (int nt = 0; nt < 8; ++nt)
                #pragma unroll
                for (int j = 0; j < 4; ++j) sc[nt][j] = ex2f(sc[nt][j]);
        }

        #pragma unroll
        for (int ks = 0; ks < 4; ++ks) {
            uint32_t pa[4];
            pa[0] = f22h2(sc[2 * ks][0],     sc[2 * ks][1]);
            pa[1] = f22h2(sc[2 * ks][2],     sc[2 * ks][3]);
            pa[2] = f22h2(sc[2 * ks + 1][0], sc[2 * ks + 1][1]);
            pa[3] = f22h2(sc[2 * ks + 1][2], sc[2 * ks + 1][3]);
            uint32_t vb[4];
            ldsm4(vb, Vts + bRow * SROW + ks * 16 + bCol);
            mma_fp16(co, pa, vb);
        }
    }

    const float linv0 = 1.f / __shfl_sync(0xffffffffu, co[0], lane | 3);
    const float linv1 = 1.f / __shfl_sync(0xffffffffu, co[2], lane | 3);
    if (tig < 3) {
        *(__half2*)(g_o + ((size_t)b * T_ + rowg0) * KPAD_ + h * E_ + 2 * tig) =
            __floats2half2_rn(co[0] * linv0, co[1] * linv0);
        *(__half2*)(g_o + ((size_t)b * T_ + rowg1) * KPAD_ + h * E_ + 2 * tig) =
            __floats2half2_rn(co[2] * linv1, co[3] * linv1);
    }
}

// ---------------- launch ----------------
extern "C" void kernel_launch(void* const* d_in, const int* in_sizes, int n_in,
                              void* d_out, int out_size) {
    const float* x     = (const float*)d_in[0];
    const float* Wq    = (const float*)d_in[1];
    const float* Wk    = (const float*)d_in[2];
    const float* Wv    = (const float*)d_in[3];
    const float* Wo    = (const float*)d_in[4];
    const float* bo    = (const float*)d_in[5];
    const float* W1    = (const float*)d_in[6];
    const float* b1    = (const float*)d_in[7];
    const float* W2    = (const float*)d_in[8];
    const float* b2    = (const float*)d_in[9];
    const float* g1    = (const float*)d_in[10];
    const float* beta1 = (const float*)d_in[11];
    const float* g2    = (const float*)d_in[12];
    const float* beta2 = (const float*)d_in[13];
    float* out = (float*)d_out;

    __half *xn, *qkv, *o, *hb, *bqkvt, *bot, *b1t, *b2t;
    float *x2;
    int *ctr1, *ctr2;
    cudaGetSymbolAddress((void**)&xn,    g_xn);
    cudaGetSymbolAddress((void**)&qkv,   g_qkv);
    cudaGetSymbolAddress((void**)&o,     g_o);
    cudaGetSymbolAddress((void**)&x2,    g_x2);
    cudaGetSymbolAddress((void**)&hb,    g_h);
    cudaGetSymbolAddress((void**)&bqkvt, g_bqkvt);
    cudaGetSymbolAddress((void**)&bot,   g_bot);
    cudaGetSymbolAddress((void**)&b1t,   g_b1t);
    cudaGetSymbolAddress((void**)&b2t,   g_b2t);
    cudaGetSymbolAddress((void**)&ctr1,  g_ctr1);
    cudaGetSymbolAddress((void**)&ctr2,  g_ctr2);

    const int SM_FFN = 3 * (128 + 128) * SROW * 2;   // 110592 B -> 2 CTAs/SM
    const int SM_QKV = 3 * (128 + 128) * SROW * 2;   // 110592 B
    const int SM_PRJ = 2 * (128 + 64) * SROW * 2;    //  55296 B -> 3 CTAs/SM
    cudaFuncSetAttribute(gemm_mma<3, 128, 3, 128, 0>, cudaFuncAttributeMaxDynamicSharedMemorySize, SM_QKV);
    cudaFuncSetAttribute(gemm_mma<2, 128, 2, 64, 0>,  cudaFuncAttributeMaxDynamicSharedMemorySize, SM_PRJ);
    cudaFuncSetAttribute(gemm_mma<1, 128, 3, 128, 1>, cudaFuncAttributeMaxDynamicSharedMemorySize, SM_FFN);
    cudaFuncSetAttribute(gemm_mma<2, 128, 3, 128, 1>, cudaFuncAttributeMaxDynamicSharedMemorySize, SM_FFN);

    // fused prep: counter reset + weight packs + g_o pad zero + LN1 (single launch)
    prep_kernel<<<NB_FIX + M_, 256>>>(Wq, Wk, Wv, Wo, W1, W2, x, g1, beta1);

    // QKV: [16384, 216(pad 256), K=768] -> fp16 qkv
    gemm_mma<3, 128, 3, 128, 0><<<dim3(2, M_ / 128), 256, SM_QKV>>>(
        xn, bqkvt, qkv, D_, QKVN_, QKVN_, nullptr, nullptr, nullptr, 0, 0);
    // attention (tensor-core flash-style) -> g_o [M, 128] fp16
    attention_tc<<<dim3(T_ / 128, H_, B_), 256>>>();
    // proj + bias + residual: x2 = x + o @ Wo + bo   [16384, 768, K=128]
    gemm_mma<2, 128, 2, 64, 0><<<dim3(D_ / 64, M_ / 128), 256, SM_PRJ>>>(
        o, bot, x2, KPAD_, D_, D_, bo, x, nullptr, 0, 0);
    // LN2 -> xn (fp16)
    layernorm_kernel<<<M_, 256>>>(x2, g2, beta2, xn);
    // FFN1: h = relu(y @ W1 + b1) -> fp16   [16384, 3072, K=768]
    // persistent 2 CTAs/SM, 128x128 tiles, dynamic
    gemm_mma<1, 128, 3, 128, 1><<<296, 256, SM_FFN>>>(
        xn, b1t, hb, D_, DFF_, DFF_, b1, nullptr, ctr1, DFF_ / 128, (DFF_ / 128) * (M_ / 128));
    // FFN2: out = x2 + h @ W2 + b2   [16384, 768, K=3072]
    gemm_mma<2, 128, 3, 128, 1><<<296, 256, SM_FFN>>>(
        hb, b2t, out, DFF_, D_, D_, b2, x2, ctr2, D_ / 128, (D_ / 128) * (M_ / 128));
}